// round 2
// baseline (speedup 1.0000x reference)
#include <cuda_runtime.h>

#define NN 16384
#define FF 128
#define CAP 96

// Scratch (no allocations allowed). Referenced ONLY from device code.
__device__ int   g_cnt[NN];
__device__ int   g_nbr[NN * CAP];
__device__ float g_deginv[NN];
__device__ float g_agg[NN * FF];
__device__ float g_h1[NN * FF];
__device__ float g_h2[NN * FF];

__global__ void zero_cnt_kernel() {
    int i = blockIdx.x * blockDim.x + threadIdx.x;
    if (i < NN) g_cnt[i] = 0;
}

// Scan dense adj (1 GB) once, build per-target neighbor lists.
// adj[r][c] != 0 means edge source r -> target c.
__global__ void build_kernel(const float* __restrict__ adj) {
    size_t idx = (size_t)blockIdx.x * blockDim.x + threadIdx.x;  // float4 index
    float4 v = reinterpret_cast<const float4*>(adj)[idx];
    int r  = (int)(idx >> 12);          // 4096 float4 per row
    int c0 = (int)((idx & 4095) << 2);  // starting column
    if (v.x != 0.0f) { int s = atomicAdd(&g_cnt[c0 + 0], 1); if (s < CAP) g_nbr[(c0 + 0) * CAP + s] = r; }
    if (v.y != 0.0f) { int s = atomicAdd(&g_cnt[c0 + 1], 1); if (s < CAP) g_nbr[(c0 + 1) * CAP + s] = r; }
    if (v.z != 0.0f) { int s = atomicAdd(&g_cnt[c0 + 2], 1); if (s < CAP) g_nbr[(c0 + 2) * CAP + s] = r; }
    if (v.w != 0.0f) { int s = atomicAdd(&g_cnt[c0 + 3], 1); if (s < CAP) g_nbr[(c0 + 3) * CAP + s] = r; }
}

__global__ void deginv_kernel() {
    int i = blockIdx.x * blockDim.x + threadIdx.x;
    if (i < NN) {
        int d = g_cnt[i];
        g_deginv[i] = (d > 0) ? (1.0f / (float)d) : 0.0f;
    }
}

// Select scratch buffer device-side. sel: 0 -> external (harness) ptr, 1 -> g_h1, 2 -> g_h2.
__device__ __forceinline__ const float* sel_in_ptr(int sel, const float* ext) {
    return sel == 0 ? ext : (sel == 1 ? g_h1 : g_h2);
}

// Mean aggregation: one block (128 threads) per target node, thread = feature.
// Writes g_agg (device symbol).
__global__ void agg_kernel(const float* __restrict__ hin_ext, int sel_in) {
    const float* hin = sel_in_ptr(sel_in, hin_ext);
    int t = blockIdx.x;
    int f = threadIdx.x;
    int deg = min(g_cnt[t], CAP);
    const int* nb = &g_nbr[t * CAP];
    float s = 0.0f;
    int i = 0;
    for (; i + 1 < deg; i += 2) {
        int s0 = nb[i], s1 = nb[i + 1];
        s += hin[(size_t)s0 * FF + f];
        s += hin[(size_t)s1 * FF + f];
    }
    if (i < deg) s += hin[(size_t)nb[i] * FF + f];
    g_agg[(size_t)t * FF + f] = s * g_deginv[t];
}

// Fused dual GEMM: out[m][o] = act( sum_k agg[m][k]*Wl[o][k] + sum_k hin[m][k]*Wr[o][k] + b[o] )
// Single GEMM with virtual K=256: A=[g_agg|hin], B=[Wl|Wr].
// Tile: BM=128, BN=64, BK=32, 256 threads, TM=8, TN=4.
template <bool RELU>
__global__ void gemm_kernel(const float* __restrict__ hin_ext, int sel_in,
                            const float* __restrict__ Wl, const float* __restrict__ Wr,
                            const float* __restrict__ bias,
                            float* __restrict__ out_ext, int sel_out,
                            int fout) {
    const float* hin = sel_in_ptr(sel_in, hin_ext);
    float* out = sel_out == 0 ? out_ext : (sel_out == 1 ? g_h1 : g_h2);

    __shared__ float As[32][128];
    __shared__ float Bs[32][64];

    int tid = threadIdx.x;
    int rowBase = blockIdx.x * 128;
    int colBase = blockIdx.y * 64;
    int tx = tid & 15;   // n direction (4 cols each)
    int ty = tid >> 4;   // m direction (8 rows each)

    float acc[8][4];
#pragma unroll
    for (int i = 0; i < 8; i++)
#pragma unroll
        for (int j = 0; j < 4; j++) acc[i][j] = 0.0f;

#pragma unroll 1
    for (int kt = 0; kt < 8; kt++) {
        int kb = kt * 32;
        const float* srcA;
        const float* srcB;
        int koff;
        if (kb < 128) { srcA = g_agg; srcB = Wl; koff = kb; }
        else          { srcA = hin;   srcB = Wr; koff = kb - 128; }

        // Load A tile: 128 rows x 32 cols = 1024 float4, 4 per thread
#pragma unroll
        for (int i = 0; i < 4; i++) {
            int lin = tid + i * 256;
            int m  = lin >> 3;
            int kq = lin & 7;
            float4 v = *reinterpret_cast<const float4*>(
                &srcA[(size_t)(rowBase + m) * FF + koff + kq * 4]);
            As[kq * 4 + 0][m] = v.x;
            As[kq * 4 + 1][m] = v.y;
            As[kq * 4 + 2][m] = v.z;
            As[kq * 4 + 3][m] = v.w;
        }
        // Load B tile: 64 rows x 32 cols = 512 float4, 2 per thread
#pragma unroll
        for (int i = 0; i < 2; i++) {
            int lin = tid + i * 256;
            int o  = lin >> 3;
            int kq = lin & 7;
            float4 v = *reinterpret_cast<const float4*>(
                &srcB[(size_t)(colBase + o) * FF + koff + kq * 4]);
            Bs[kq * 4 + 0][o] = v.x;
            Bs[kq * 4 + 1][o] = v.y;
            Bs[kq * 4 + 2][o] = v.z;
            Bs[kq * 4 + 3][o] = v.w;
        }
        __syncthreads();

#pragma unroll
        for (int kk = 0; kk < 32; kk++) {
            float4 a0 = *reinterpret_cast<float4*>(&As[kk][ty * 8]);
            float4 a1 = *reinterpret_cast<float4*>(&As[kk][ty * 8 + 4]);
            float4 b0 = *reinterpret_cast<float4*>(&Bs[kk][tx * 4]);
            float am[8] = {a0.x, a0.y, a0.z, a0.w, a1.x, a1.y, a1.z, a1.w};
            float bn[4] = {b0.x, b0.y, b0.z, b0.w};
#pragma unroll
            for (int i = 0; i < 8; i++)
#pragma unroll
                for (int j = 0; j < 4; j++)
                    acc[i][j] = fmaf(am[i], bn[j], acc[i][j]);
        }
        __syncthreads();
    }

    // Epilogue: +bias, optional relu
#pragma unroll
    for (int i = 0; i < 8; i++) {
        int m = rowBase + ty * 8 + i;
#pragma unroll
        for (int j = 0; j < 4; j++) {
            int o = colBase + tx * 4 + j;
            float v = acc[i][j] + bias[o];
            if (RELU) v = fmaxf(v, 0.0f);
            out[(size_t)m * fout + o] = v;
        }
    }
}

extern "C" void kernel_launch(void* const* d_in, const int* in_sizes, int n_in,
                              void* d_out, int out_size) {
    const float* x   = (const float*)d_in[0];
    const float* adj = (const float*)d_in[1];
    const float* Wl0 = (const float*)d_in[2];
    const float* b0  = (const float*)d_in[3];
    const float* Wr0 = (const float*)d_in[4];
    const float* Wl1 = (const float*)d_in[5];
    const float* b1  = (const float*)d_in[6];
    const float* Wr1 = (const float*)d_in[7];
    const float* Wl2 = (const float*)d_in[8];
    const float* b2  = (const float*)d_in[9];
    const float* Wr2 = (const float*)d_in[10];
    float* out = (float*)d_out;

    // 1. Build sparse neighbor lists from dense adj (reads 1 GB once)
    zero_cnt_kernel<<<NN / 256, 256>>>();
    {
        size_t nf4 = (size_t)NN * NN / 4;
        build_kernel<<<(unsigned)(nf4 / 256), 256>>>(adj);
    }
    deginv_kernel<<<NN / 256, 256>>>();

    dim3 g2(NN / 128, 2);  // fout=128
    dim3 g1(NN / 128, 1);  // fout=64

    // Layer 0: agg(x) ; h1 = relu(dualgemm(agg, x))
    agg_kernel<<<NN, FF>>>(x, 0);
    gemm_kernel<true><<<g2, 256>>>(x, 0, Wl0, Wr0, b0, nullptr, 1, 128);
    // Layer 1: agg(h1) ; h2 = relu(dualgemm(agg, h1))
    agg_kernel<<<NN, FF>>>(nullptr, 1);
    gemm_kernel<true><<<g2, 256>>>(nullptr, 1, Wl1, Wr1, b1, nullptr, 2, 128);
    // Layer 2: agg(h2) ; out = dualgemm(agg, h2)
    agg_kernel<<<NN, FF>>>(nullptr, 2);
    gemm_kernel<false><<<g1, 256>>>(nullptr, 2, Wl2, Wr2, b2, out, 0, 64);
}

// round 4
// speedup vs baseline: 1.1435x; 1.1435x over previous
#include <cuda_runtime.h>

#define NN 16384
#define CAP 96
#define GEMM0_BLOCKS 512
#define BUILD_BLOCKS 32768

// Scratch (no allocations). Referenced ONLY from device code.
__device__ int   g_cnt[NN];
__device__ int   g_nbr[NN * CAP];
__device__ float g_z[NN * 128];
__device__ float g_r[NN * 128];
__device__ float g_h[NN * 128];

__global__ void zero_cnt_kernel() {
    int i = blockIdx.x * blockDim.x + threadIdx.x;
    if (i < NN) g_cnt[i] = 0;
}

// ---------------------------------------------------------------------------
// GEMM block: computes a 128x64 output tile of  A[N,128] @ B[fout,128]^T.
// Virtual column space = 2*fout: first fout cols -> g_z (B=Wl), rest -> g_r
// (B=Wr, +bias). K = 128 fixed. 256 threads, TM=8 x TN=4.
// ---------------------------------------------------------------------------
__device__ __forceinline__ void gemm_block(
    const float* __restrict__ A,
    const float* __restrict__ Wl, const float* __restrict__ Wr,
    const float* __restrict__ bias, int fout, int rb, int cb,
    float (*As)[128], float (*Bs)[64])
{
    int tid = threadIdx.x;
    int rowBase = rb * 128;
    int vcol = cb * 64;

    const float* B;
    float* out;
    int colBase;
    bool addb;
    if (vcol < fout) { B = Wl; out = g_z; colBase = vcol;        addb = false; }
    else             { B = Wr; out = g_r; colBase = vcol - fout; addb = true;  }

    int tx = tid & 15;   // n direction (4 cols each)
    int ty = tid >> 4;   // m direction (8 rows each)

    float acc[8][4];
#pragma unroll
    for (int i = 0; i < 8; i++)
#pragma unroll
        for (int j = 0; j < 4; j++) acc[i][j] = 0.0f;

#pragma unroll 1
    for (int kt = 0; kt < 4; kt++) {
        int koff = kt * 32;
        // A tile: 128 rows x 32 cols = 1024 float4, 4 per thread
#pragma unroll
        for (int i = 0; i < 4; i++) {
            int lin = tid + i * 256;
            int m = lin >> 3;
            int kq = lin & 7;
            float4 v = *reinterpret_cast<const float4*>(
                &A[(size_t)(rowBase + m) * 128 + koff + kq * 4]);
            As[kq * 4 + 0][m] = v.x;
            As[kq * 4 + 1][m] = v.y;
            As[kq * 4 + 2][m] = v.z;
            As[kq * 4 + 3][m] = v.w;
        }
        // B tile: 64 rows x 32 cols = 512 float4, 2 per thread
#pragma unroll
        for (int i = 0; i < 2; i++) {
            int lin = tid + i * 256;
            int o = lin >> 3;
            int kq = lin & 7;
            float4 v = *reinterpret_cast<const float4*>(
                &B[(size_t)(colBase + o) * 128 + koff + kq * 4]);
            Bs[kq * 4 + 0][o] = v.x;
            Bs[kq * 4 + 1][o] = v.y;
            Bs[kq * 4 + 2][o] = v.z;
            Bs[kq * 4 + 3][o] = v.w;
        }
        __syncthreads();

#pragma unroll
        for (int kk = 0; kk < 32; kk++) {
            float4 a0 = *reinterpret_cast<float4*>(&As[kk][ty * 8]);
            float4 a1 = *reinterpret_cast<float4*>(&As[kk][ty * 8 + 4]);
            float4 b0 = *reinterpret_cast<float4*>(&Bs[kk][tx * 4]);
            float am[8] = {a0.x, a0.y, a0.z, a0.w, a1.x, a1.y, a1.z, a1.w};
            float bn[4] = {b0.x, b0.y, b0.z, b0.w};
#pragma unroll
            for (int i = 0; i < 8; i++)
#pragma unroll
                for (int j = 0; j < 4; j++)
                    acc[i][j] = fmaf(am[i], bn[j], acc[i][j]);
        }
        __syncthreads();
    }

#pragma unroll
    for (int i = 0; i < 8; i++) {
        int m = rowBase + ty * 8 + i;
#pragma unroll
        for (int j = 0; j < 4; j++) {
            int o = colBase + tx * 4 + j;
            float v = acc[i][j];
            if (addb) v += bias[o];
            out[(size_t)m * fout + o] = v;
        }
    }
}

// ---------------------------------------------------------------------------
// Fused kernel: blocks [0, GEMM0_BLOCKS) do layer-0 transform (x -> g_z, g_r),
// remaining BUILD_BLOCKS scan the 1 GB dense adj and build neighbor lists.
// The two halves are independent; fma-bound GEMM hides under dram-bound scan.
// ---------------------------------------------------------------------------
__global__ void __launch_bounds__(256) fused_gemm0_build_kernel(
    const float* __restrict__ x, const float* __restrict__ adj,
    const float* __restrict__ Wl0, const float* __restrict__ Wr0,
    const float* __restrict__ b0)
{
    __shared__ float As[32][128];
    __shared__ float Bs[32][64];

    int bid = blockIdx.x;
    if (bid < GEMM0_BLOCKS) {
        gemm_block(x, Wl0, Wr0, b0, 128, bid >> 2, bid & 3, As, Bs);
        return;
    }

    // Build: each thread reads 8 float4 (128 B), coalesced per iteration.
    int bb = bid - GEMM0_BLOCKS;
    const float4* adj4 = reinterpret_cast<const float4*>(adj);
    size_t base = (size_t)bb * 2048 + threadIdx.x;

    float4 v[8];
#pragma unroll
    for (int i = 0; i < 8; i++) v[i] = __ldcs(&adj4[base + (size_t)i * 256]);

#pragma unroll
    for (int i = 0; i < 8; i++) {
        size_t idx = base + (size_t)i * 256;
        int r  = (int)(idx >> 12);          // 4096 float4 per adj row
        int c0 = (int)((idx & 4095) << 2);
        if (v[i].x != 0.0f) { int s = atomicAdd(&g_cnt[c0 + 0], 1); if (s < CAP) g_nbr[(c0 + 0) * CAP + s] = r; }
        if (v[i].y != 0.0f) { int s = atomicAdd(&g_cnt[c0 + 1], 1); if (s < CAP) g_nbr[(c0 + 1) * CAP + s] = r; }
        if (v[i].z != 0.0f) { int s = atomicAdd(&g_cnt[c0 + 2], 1); if (s < CAP) g_nbr[(c0 + 2) * CAP + s] = r; }
        if (v[i].w != 0.0f) { int s = atomicAdd(&g_cnt[c0 + 3], 1); if (s < CAP) g_nbr[(c0 + 3) * CAP + s] = r; }
    }
}

// Standalone GEMM for layers 1 and 2 (A = g_h).
__global__ void __launch_bounds__(256) gemm_kernel(
    const float* __restrict__ Wl, const float* __restrict__ Wr,
    const float* __restrict__ bias, int fout)
{
    __shared__ float As[32][128];
    __shared__ float Bs[32][64];
    gemm_block(g_h, Wl, Wr, bias, fout, blockIdx.x, blockIdx.y, As, Bs);
}

__device__ __forceinline__ float4 f4add(float4 a, float4 b) {
    return make_float4(a.x + b.x, a.y + b.y, a.z + b.z, a.w + b.w);
}

// ---------------------------------------------------------------------------
// Gather: h[t] = act( deginv[t] * sum_{n in nbr(t)} z[n]  +  r[t] )
// Warp-level: F/4 lanes per target, float4 per lane, unroll 4 (int4 nbr fetch).
// ---------------------------------------------------------------------------
template <int F, bool RELU>
__global__ void gather_kernel(float* __restrict__ out_ext, int sel_out) {
    constexpr int TPT = F / 4;        // threads per target (32 or 16)
    constexpr int TGT_PER_BLK = 128 / TPT;

    float* out = (sel_out == 0) ? out_ext : g_h;
    int lin = threadIdx.x;
    int t = blockIdx.x * TGT_PER_BLK + lin / TPT;
    int c = lin % TPT;                // float4 column

    int deg = min(g_cnt[t], CAP);
    const int* nb = &g_nbr[t * CAP];
    const float4* z4 = reinterpret_cast<const float4*>(g_z);

    float4 s = make_float4(0.f, 0.f, 0.f, 0.f);
    int i = 0;
    for (; i + 4 <= deg; i += 4) {
        int4 nn = *reinterpret_cast<const int4*>(&nb[i]);
        float4 a = z4[(size_t)nn.x * TPT + c];
        float4 b = z4[(size_t)nn.y * TPT + c];
        float4 cc = z4[(size_t)nn.z * TPT + c];
        float4 d = z4[(size_t)nn.w * TPT + c];
        s = f4add(s, f4add(f4add(a, b), f4add(cc, d)));
    }
    for (; i < deg; i++)
        s = f4add(s, z4[(size_t)nb[i] * TPT + c]);

    float dinv = (deg > 0) ? (1.0f / (float)deg) : 0.0f;
    float4 rr = reinterpret_cast<const float4*>(g_r)[(size_t)t * TPT + c];
    float4 o;
    o.x = s.x * dinv + rr.x;
    o.y = s.y * dinv + rr.y;
    o.z = s.z * dinv + rr.z;
    o.w = s.w * dinv + rr.w;
    if (RELU) {
        o.x = fmaxf(o.x, 0.f); o.y = fmaxf(o.y, 0.f);
        o.z = fmaxf(o.z, 0.f); o.w = fmaxf(o.w, 0.f);
    }
    reinterpret_cast<float4*>(out)[(size_t)t * TPT + c] = o;
}

extern "C" void kernel_launch(void* const* d_in, const int* in_sizes, int n_in,
                              void* d_out, int out_size) {
    const float* x   = (const float*)d_in[0];
    const float* adj = (const float*)d_in[1];
    const float* Wl0 = (const float*)d_in[2];
    const float* b0  = (const float*)d_in[3];
    const float* Wr0 = (const float*)d_in[4];
    const float* Wl1 = (const float*)d_in[5];
    const float* b1  = (const float*)d_in[6];
    const float* Wr1 = (const float*)d_in[7];
    const float* Wl2 = (const float*)d_in[8];
    const float* b2  = (const float*)d_in[9];
    const float* Wr2 = (const float*)d_in[10];
    float* out = (float*)d_out;

    zero_cnt_kernel<<<NN / 256, 256>>>();

    // Layer-0 transform (x -> z,r) overlapped with adjacency scan.
    fused_gemm0_build_kernel<<<GEMM0_BLOCKS + BUILD_BLOCKS, 256>>>(x, adj, Wl0, Wr0, b0);

    // Layer 0 aggregate+activate: g_h = relu(mean(z) + r)
    gather_kernel<128, true><<<NN / 4, 128>>>(nullptr, 1);

    // Layer 1
    gemm_kernel<<<dim3(NN / 128, 4), 256>>>(Wl1, Wr1, b1, 128);
    gather_kernel<128, true><<<NN / 4, 128>>>(nullptr, 1);

    // Layer 2 (fout = 64), final gather writes d_out, no relu
    gemm_kernel<<<dim3(NN / 128, 2), 256>>>(Wl2, Wr2, b2, 64);
    gather_kernel<64, false><<<NN / 8, 128>>>(out, 0);
}